// round 3
// baseline (speedup 1.0000x reference)
#include <cuda_runtime.h>
#include <math.h>

// Problem constants
static constexpr int BB   = 2;
static constexpr int SS   = 2048;
static constexpr int HH   = 1024;
static constexpr int NH   = 16;
static constexpr int HD   = 64;
static constexpr int MTOT = BB * SS;  // 4096 rows

// Scratch (static device globals; no dynamic allocation allowed)
__device__ float g_Q[(size_t)BB * NH * SS * HD];   // [bh][s][d]
__device__ float g_K[(size_t)BB * NH * SS * HD];
__device__ float g_V[(size_t)BB * NH * SS * HD];
__device__ float g_ctx[(size_t)MTOT * HH];         // row-major (b*S+s, H)
__device__ float g_y[(size_t)MTOT * HH];           // pre-LN: ctx@Wo + bo + x

// ---------------------------------------------------------------------------
// QKV GEMM: out = x @ W + b, scattered to head-major [b*NH+h][s][d]
// 128x128 tile, BK=16, 256 threads, 8x8 per thread.
// blockIdx.z in {0,1,2} selects Q/K/V.
// ---------------------------------------------------------------------------
__global__ __launch_bounds__(256) void qkv_gemm_kernel(
    const float* __restrict__ x,
    const float* __restrict__ Wq, const float* __restrict__ bq,
    const float* __restrict__ Wk, const float* __restrict__ bk,
    const float* __restrict__ Wv, const float* __restrict__ bv)
{
    const int mat = blockIdx.z;
    const float* W    = (mat == 0) ? Wq : (mat == 1 ? Wk : Wv);
    const float* bias = (mat == 0) ? bq : (mat == 1 ? bk : bv);
    float* out        = (mat == 0) ? g_Q : (mat == 1 ? g_K : g_V);

    __shared__ float As[16][128];
    __shared__ float Bs[16][128];

    const int tid = threadIdx.x;
    const int tx  = tid & 15;
    const int ty  = tid >> 4;
    const int m0  = blockIdx.y * 128;
    const int n0  = blockIdx.x * 128;

    float acc[8][8];
#pragma unroll
    for (int i = 0; i < 8; i++)
#pragma unroll
        for (int j = 0; j < 8; j++) acc[i][j] = 0.0f;

    for (int k0 = 0; k0 < HH; k0 += 16) {
        // Load A tile (128 rows x 16 cols), store transposed As[k][m]
#pragma unroll
        for (int t = tid; t < 512; t += 256) {
            int row = t >> 2;
            int c4  = t & 3;
            float4 v = *(const float4*)(x + (size_t)(m0 + row) * HH + k0 + c4 * 4);
            As[c4 * 4 + 0][row] = v.x;
            As[c4 * 4 + 1][row] = v.y;
            As[c4 * 4 + 2][row] = v.z;
            As[c4 * 4 + 3][row] = v.w;
        }
        // Load B tile (16 rows x 128 cols)
#pragma unroll
        for (int t = tid; t < 512; t += 256) {
            int row = t >> 5;
            int c4  = t & 31;
            *(float4*)&Bs[row][c4 * 4] =
                *(const float4*)(W + (size_t)(k0 + row) * HH + n0 + c4 * 4);
        }
        __syncthreads();

#pragma unroll
        for (int kk = 0; kk < 16; kk++) {
            float a[8], bf[8];
            *(float4*)&a[0]  = *(float4*)&As[kk][ty * 8];
            *(float4*)&a[4]  = *(float4*)&As[kk][ty * 8 + 4];
            *(float4*)&bf[0] = *(float4*)&Bs[kk][tx * 8];
            *(float4*)&bf[4] = *(float4*)&Bs[kk][tx * 8 + 4];
#pragma unroll
            for (int i = 0; i < 8; i++)
#pragma unroll
                for (int j = 0; j < 8; j++)
                    acc[i][j] += a[i] * bf[j];
        }
        __syncthreads();
    }

    // Epilogue: add bias, scatter into head-major layout.
    // nbase is a multiple of 8, so all 8 cols live in the same head.
    const int nbase = n0 + tx * 8;       // [0, 1024)
    const int h = nbase >> 6;
    const int d = nbase & 63;
#pragma unroll
    for (int i = 0; i < 8; i++) {
        int m = m0 + ty * 8 + i;
        int b = m >> 11;      // /2048
        int s = m & 2047;
        float* o = out + (((size_t)(b * NH + h) * SS) + s) * HD + d;
#pragma unroll
        for (int j = 0; j < 8; j++)
            o[j] = acc[i][j] + bias[nbase + j];
    }
}

// ---------------------------------------------------------------------------
// Flash attention: one query row per thread, 128 rows per block.
// K/V streamed through smem in 64-key tiles; online softmax in 16-key chunks.
// Matches ref: scores = QK^T/8, clip(+-1e4), softmax, ctx = attn @ V.
// ---------------------------------------------------------------------------
__global__ __launch_bounds__(128) void flash_kernel()
{
    const int bh   = blockIdx.y;          // b*NH + h
    const int b    = bh >> 4;
    const int h    = bh & 15;
    const int qrow = blockIdx.x * 128 + threadIdx.x;

    __shared__ float4 Ks4[64 * 16];       // 64 keys x 64 dims
    __shared__ float4 Vs4[64 * 16];

    // Load q row, pre-scaled by 1/sqrt(HD) = 0.125
    float qreg[64];
    {
        const float4* qp = (const float4*)(g_Q + ((size_t)bh * SS + qrow) * HD);
#pragma unroll
        for (int i = 0; i < 16; i++) {
            float4 t = qp[i];
            qreg[4 * i + 0] = t.x * 0.125f;
            qreg[4 * i + 1] = t.y * 0.125f;
            qreg[4 * i + 2] = t.z * 0.125f;
            qreg[4 * i + 3] = t.w * 0.125f;
        }
    }

    float accv[64];
#pragma unroll
    for (int d = 0; d < 64; d++) accv[d] = 0.0f;
    float m = -1e30f;
    float l = 0.0f;

    const float4* Kg = (const float4*)(g_K + (size_t)bh * SS * HD);
    const float4* Vg = (const float4*)(g_V + (size_t)bh * SS * HD);

    for (int kt = 0; kt < SS / 64; kt++) {
        // Stage K/V tile (coalesced)
        const float4* Kt = Kg + (size_t)kt * 64 * 16;
        const float4* Vt = Vg + (size_t)kt * 64 * 16;
#pragma unroll
        for (int i = 0; i < 8; i++) {
            int idx = threadIdx.x + i * 128;
            Ks4[idx] = Kt[idx];
            Vs4[idx] = Vt[idx];
        }
        __syncthreads();

#pragma unroll 1
        for (int ch = 0; ch < 4; ch++) {
            float s[16];
#pragma unroll
            for (int jj = 0; jj < 16; jj++) {
                const float4* kp = Ks4 + (ch * 16 + jj) * 16;
                float a = 0.0f;
#pragma unroll
                for (int d = 0; d < 16; d++) {
                    float4 kv = kp[d];   // broadcast across warp
                    a += qreg[4 * d + 0] * kv.x;
                    a += qreg[4 * d + 1] * kv.y;
                    a += qreg[4 * d + 2] * kv.z;
                    a += qreg[4 * d + 3] * kv.w;
                }
                // clip to [-10000, 10000] (reference semantics)
                s[jj] = fminf(fmaxf(a, -10000.0f), 10000.0f);
            }
            float cmax = m;
#pragma unroll
            for (int jj = 0; jj < 16; jj++) cmax = fmaxf(cmax, s[jj]);
            float alpha = __expf(m - cmax);
            m = cmax;
            l *= alpha;
#pragma unroll
            for (int d = 0; d < 64; d++) accv[d] *= alpha;
#pragma unroll
            for (int jj = 0; jj < 16; jj++) {
                float p = __expf(s[jj] - m);
                l += p;
                const float4* vp = Vs4 + (ch * 16 + jj) * 16;
#pragma unroll
                for (int d = 0; d < 16; d++) {
                    float4 vv = vp[d];
                    accv[4 * d + 0] += p * vv.x;
                    accv[4 * d + 1] += p * vv.y;
                    accv[4 * d + 2] += p * vv.z;
                    accv[4 * d + 3] += p * vv.w;
                }
            }
        }
        __syncthreads();
    }

    // Normalize and write ctx row-major (b*S+s, H) with head offset
    const float inv = 1.0f / l;
    float4* op = (float4*)(g_ctx + ((size_t)(b * SS + qrow)) * HH + h * HD);
#pragma unroll
    for (int d = 0; d < 16; d++) {
        float4 o;
        o.x = accv[4 * d + 0] * inv;
        o.y = accv[4 * d + 1] * inv;
        o.z = accv[4 * d + 2] * inv;
        o.w = accv[4 * d + 3] * inv;
        op[d] = o;
    }
}

// ---------------------------------------------------------------------------
// O projection: y = ctx @ Wo + bo + x  (residual fused into epilogue)
// ---------------------------------------------------------------------------
__global__ __launch_bounds__(256) void oproj_gemm_kernel(
    const float* __restrict__ x,
    const float* __restrict__ Wo, const float* __restrict__ bo)
{
    __shared__ float As[16][128];
    __shared__ float Bs[16][128];

    const int tid = threadIdx.x;
    const int tx  = tid & 15;
    const int ty  = tid >> 4;
    const int m0  = blockIdx.y * 128;
    const int n0  = blockIdx.x * 128;

    float acc[8][8];
#pragma unroll
    for (int i = 0; i < 8; i++)
#pragma unroll
        for (int j = 0; j < 8; j++) acc[i][j] = 0.0f;

    for (int k0 = 0; k0 < HH; k0 += 16) {
#pragma unroll
        for (int t = tid; t < 512; t += 256) {
            int row = t >> 2;
            int c4  = t & 3;
            float4 v = *(const float4*)(g_ctx + (size_t)(m0 + row) * HH + k0 + c4 * 4);
            As[c4 * 4 + 0][row] = v.x;
            As[c4 * 4 + 1][row] = v.y;
            As[c4 * 4 + 2][row] = v.z;
            As[c4 * 4 + 3][row] = v.w;
        }
#pragma unroll
        for (int t = tid; t < 512; t += 256) {
            int row = t >> 5;
            int c4  = t & 31;
            *(float4*)&Bs[row][c4 * 4] =
                *(const float4*)(Wo + (size_t)(k0 + row) * HH + n0 + c4 * 4);
        }
        __syncthreads();

#pragma unroll
        for (int kk = 0; kk < 16; kk++) {
            float a[8], bf[8];
            *(float4*)&a[0]  = *(float4*)&As[kk][ty * 8];
            *(float4*)&a[4]  = *(float4*)&As[kk][ty * 8 + 4];
            *(float4*)&bf[0] = *(float4*)&Bs[kk][tx * 8];
            *(float4*)&bf[4] = *(float4*)&Bs[kk][tx * 8 + 4];
#pragma unroll
            for (int i = 0; i < 8; i++)
#pragma unroll
                for (int j = 0; j < 8; j++)
                    acc[i][j] += a[i] * bf[j];
        }
        __syncthreads();
    }

    const int nbase = n0 + tx * 8;
#pragma unroll
    for (int i = 0; i < 8; i++) {
        int m = m0 + ty * 8 + i;
        float*       yo = g_y + (size_t)m * HH + nbase;
        const float* xr = x   + (size_t)m * HH + nbase;
#pragma unroll
        for (int j = 0; j < 8; j++)
            yo[j] = acc[i][j] + bo[nbase + j] + xr[j];
    }
}

// ---------------------------------------------------------------------------
// LayerNorm over last dim (1024), one block per row.
// ---------------------------------------------------------------------------
__global__ __launch_bounds__(256) void ln_kernel(
    const float* __restrict__ gamma, const float* __restrict__ beta,
    float* __restrict__ out)
{
    __shared__ float red[256];
    const int row = blockIdx.x;
    const int tid = threadIdx.x;

    const float4* yp = (const float4*)(g_y + (size_t)row * HH);
    float4 v = yp[tid];

    // mean
    float s = v.x + v.y + v.z + v.w;
    red[tid] = s;
    __syncthreads();
    for (int off = 128; off > 0; off >>= 1) {
        if (tid < off) red[tid] += red[tid + off];
        __syncthreads();
    }
    const float mu = red[0] * (1.0f / HH);
    __syncthreads();

    // variance
    float dx = v.x - mu, dy = v.y - mu, dz = v.z - mu, dw = v.w - mu;
    red[tid] = dx * dx + dy * dy + dz * dz + dw * dw;
    __syncthreads();
    for (int off = 128; off > 0; off >>= 1) {
        if (tid < off) red[tid] += red[tid + off];
        __syncthreads();
    }
    const float var = red[0] * (1.0f / HH);
    const float inv = rsqrtf(var + 1e-5f);

    const float4 g  = ((const float4*)gamma)[tid];
    const float4 be = ((const float4*)beta)[tid];
    float4 o;
    o.x = dx * inv * g.x + be.x;
    o.y = dy * inv * g.y + be.y;
    o.z = dz * inv * g.z + be.z;
    o.w = dw * inv * g.w + be.w;
    ((float4*)out)[(size_t)row * (HH / 4) + tid] = o;
}

// ---------------------------------------------------------------------------
extern "C" void kernel_launch(void* const* d_in, const int* in_sizes, int n_in,
                              void* d_out, int out_size)
{
    (void)in_sizes; (void)n_in; (void)out_size;
    const float* x  = (const float*)d_in[0];
    const float* Wq = (const float*)d_in[1];
    const float* bq = (const float*)d_in[2];
    const float* Wk = (const float*)d_in[3];
    const float* bk = (const float*)d_in[4];
    const float* Wv = (const float*)d_in[5];
    const float* bv = (const float*)d_in[6];
    const float* Wo = (const float*)d_in[7];
    const float* bo = (const float*)d_in[8];
    const float* ga = (const float*)d_in[9];
    const float* be = (const float*)d_in[10];
    float* out = (float*)d_out;

    dim3 gq(HH / 128, MTOT / 128, 3);
    qkv_gemm_kernel<<<gq, 256>>>(x, Wq, bq, Wk, bk, Wv, bv);

    dim3 gf(SS / 128, BB * NH);
    flash_kernel<<<gf, 128>>>();

    dim3 go(HH / 128, MTOT / 128);
    oproj_gemm_kernel<<<go, 256>>>(x, Wo, bo);

    ln_kernel<<<MTOT, 256>>>(ga, be, out);
}

// round 5
// speedup vs baseline: 1.1195x; 1.1195x over previous
#include <cuda_runtime.h>
#include <stdint.h>
#include <math.h>

// Problem constants
static constexpr int BB   = 2;
static constexpr int SS   = 2048;
static constexpr int HH   = 1024;
static constexpr int NH   = 16;
static constexpr int HD   = 64;
static constexpr int MTOT = BB * SS;  // 4096 rows

// Scratch (static device globals; no dynamic allocation allowed)
__device__ float g_Q[(size_t)BB * NH * SS * HD];   // [bh][s][d]
__device__ float g_K[(size_t)BB * NH * SS * HD];
__device__ float g_V[(size_t)BB * NH * SS * HD];
__device__ float g_ctx[(size_t)MTOT * HH];         // row-major (b*S+s, H)
__device__ float g_y[(size_t)MTOT * HH];           // pre-LN: ctx@Wo + bo + x

// ---------------------------------------------------------------------------
// tf32 helpers (3xTF32 decomposition for ~fp32 accuracy on tensor cores)
// ---------------------------------------------------------------------------
__device__ __forceinline__ uint32_t f2tf(float x) {
    uint32_t r;
    asm("cvt.rna.tf32.f32 %0, %1;" : "=r"(r) : "f"(x));
    return r;
}

__device__ __forceinline__ void mma8(float c[4], const uint32_t a[4], const uint32_t b[2]) {
    asm volatile(
        "mma.sync.aligned.m16n8k8.row.col.f32.tf32.tf32.f32 "
        "{%0,%1,%2,%3}, {%4,%5,%6,%7}, {%8,%9}, {%0,%1,%2,%3};"
        : "+f"(c[0]), "+f"(c[1]), "+f"(c[2]), "+f"(c[3])
        : "r"(a[0]), "r"(a[1]), "r"(a[2]), "r"(a[3]), "r"(b[0]), "r"(b[1]));
}

// ---------------------------------------------------------------------------
// 128x128x1024 tf32 mma mainloop (3xTF32). 256 threads, 8 warps (2m x 4n),
// warp tile 64x32, mma tile m16n8k8.
// As[128][36] row-major (stride 36 -> conflict-free A-frag loads),
// Bs[32][136] k-major  (stride 136 -> conflict-free B-frag loads).
// acc[mt][nt][r] per thread (mt: 4 m16 tiles, nt: 4 n8 tiles).
// ---------------------------------------------------------------------------
static constexpr int AS_ST = 36;
static constexpr int BS_ST = 136;

__device__ __forceinline__ void gemm128_mainloop(
    const float* __restrict__ A, const float* __restrict__ B,
    float* As, float* Bs, float acc[4][4][4])
{
    const int tid  = threadIdx.x;
    const int m0   = blockIdx.y * 128;
    const int n0   = blockIdx.x * 128;
    const int warp = tid >> 5;
    const int lane = tid & 31;
    const int gid  = lane >> 2;   // groupID (0..7)
    const int t4   = lane & 3;    // thread-in-group (0..3)
    const int warp_m = (warp >> 2) * 64;
    const int warp_n = (warp & 3) * 32;

    // gmem staging assignment
    const int arow = tid >> 3;    // 0..31 (A rows, +32*r)
    const int ac4  = tid & 7;     // 0..7  (A col groups of 4)
    const int brow = tid >> 5;    // 0..7  (B rows, +8*r)
    const int bc4  = tid & 31;    // 0..31 (B col groups of 4)

#pragma unroll
    for (int mt = 0; mt < 4; mt++)
#pragma unroll
        for (int nt = 0; nt < 4; nt++)
#pragma unroll
            for (int r = 0; r < 4; r++) acc[mt][nt][r] = 0.0f;

    const float* ag = A + (size_t)(m0 + arow) * HH + ac4 * 4;
    const float* bg = B + (size_t)brow * HH + n0 + bc4 * 4;

    float4 aR[4], bR[4];
#pragma unroll
    for (int r = 0; r < 4; r++) {
        aR[r] = *(const float4*)(ag + (size_t)(32 * r) * HH);
        bR[r] = *(const float4*)(bg + (size_t)(8 * r) * HH);
    }

    for (int k0 = 0; k0 < HH; k0 += 32) {
        // stage to smem
#pragma unroll
        for (int r = 0; r < 4; r++) {
            *(float4*)&As[(arow + 32 * r) * AS_ST + ac4 * 4] = aR[r];
            *(float4*)&Bs[(brow + 8 * r) * BS_ST + bc4 * 4]  = bR[r];
        }
        __syncthreads();

        // prefetch next tile
        if (k0 + 32 < HH) {
            const float* ag2 = ag + (k0 + 32);
            const float* bg2 = bg + (size_t)(k0 + 32) * HH;
#pragma unroll
            for (int r = 0; r < 4; r++) {
                aR[r] = *(const float4*)(ag2 + (size_t)(32 * r) * HH);
                bR[r] = *(const float4*)(bg2 + (size_t)(8 * r) * HH);
            }
        }

        // compute 4 k8 steps
#pragma unroll
        for (int ks = 0; ks < 4; ks++) {
            uint32_t Ahi[4][4], Alo[4][4];
#pragma unroll
            for (int mt = 0; mt < 4; mt++) {
                int base = (warp_m + mt * 16 + gid) * AS_ST + ks * 8 + t4;
                float a0 = As[base];
                float a1 = As[base + 8 * AS_ST];
                float a2 = As[base + 4];
                float a3 = As[base + 8 * AS_ST + 4];
                Ahi[mt][0] = f2tf(a0); Alo[mt][0] = f2tf(a0 - __uint_as_float(Ahi[mt][0]));
                Ahi[mt][1] = f2tf(a1); Alo[mt][1] = f2tf(a1 - __uint_as_float(Ahi[mt][1]));
                Ahi[mt][2] = f2tf(a2); Alo[mt][2] = f2tf(a2 - __uint_as_float(Ahi[mt][2]));
                Ahi[mt][3] = f2tf(a3); Alo[mt][3] = f2tf(a3 - __uint_as_float(Ahi[mt][3]));
            }
            uint32_t Bhi[4][2], Blo[4][2];
#pragma unroll
            for (int nt = 0; nt < 4; nt++) {
                int cb = (ks * 8 + t4) * BS_ST + warp_n + nt * 8 + gid;
                float b0 = Bs[cb];
                float b1 = Bs[cb + 4 * BS_ST];
                Bhi[nt][0] = f2tf(b0); Blo[nt][0] = f2tf(b0 - __uint_as_float(Bhi[nt][0]));
                Bhi[nt][1] = f2tf(b1); Blo[nt][1] = f2tf(b1 - __uint_as_float(Bhi[nt][1]));
            }
#pragma unroll
            for (int mt = 0; mt < 4; mt++)
#pragma unroll
                for (int nt = 0; nt < 4; nt++) {
                    mma8(acc[mt][nt], Ahi[mt], Bhi[nt]);
                    mma8(acc[mt][nt], Ahi[mt], Blo[nt]);
                    mma8(acc[mt][nt], Alo[mt], Bhi[nt]);
                }
        }
        __syncthreads();
    }
}

// ---------------------------------------------------------------------------
// QKV GEMM (tensor core): out = x @ W + b, scattered head-major.
// blockIdx.z selects Q/K/V.
// ---------------------------------------------------------------------------
__global__ __launch_bounds__(256, 1) void qkv_gemm_kernel(
    const float* __restrict__ x,
    const float* __restrict__ Wq, const float* __restrict__ bq,
    const float* __restrict__ Wk, const float* __restrict__ bk,
    const float* __restrict__ Wv, const float* __restrict__ bv)
{
    const int mat = blockIdx.z;
    const float* W    = (mat == 0) ? Wq : (mat == 1 ? Wk : Wv);
    const float* bias = (mat == 0) ? bq : (mat == 1 ? bk : bv);
    float* out        = (mat == 0) ? g_Q : (mat == 1 ? g_K : g_V);

    __shared__ __align__(16) float As[128 * AS_ST];
    __shared__ __align__(16) float Bs[32 * BS_ST];

    float acc[4][4][4];
    gemm128_mainloop(x, W, As, Bs, acc);

    const int tid  = threadIdx.x;
    const int warp = tid >> 5;
    const int lane = tid & 31;
    const int gid  = lane >> 2;
    const int t4   = lane & 3;
    const int warp_m = (warp >> 2) * 64;
    const int warp_n = (warp & 3) * 32;
    const int m0 = blockIdx.y * 128;
    const int n0 = blockIdx.x * 128;

#pragma unroll
    for (int mt = 0; mt < 4; mt++) {
        const int mrow = m0 + warp_m + mt * 16 + gid;
#pragma unroll
        for (int nt = 0; nt < 4; nt++) {
            const int n = n0 + warp_n + nt * 8 + t4 * 2;
            const int h = n >> 6;
            const int d = n & 63;
            const float bx = bias[n], by = bias[n + 1];
            // row mrow
            {
                int b = mrow >> 11, s = mrow & 2047;
                float* o = out + (((size_t)(b * NH + h) * SS) + s) * HD + d;
                *(float2*)o = make_float2(acc[mt][nt][0] + bx, acc[mt][nt][1] + by);
            }
            // row mrow + 8
            {
                int m2 = mrow + 8;
                int b = m2 >> 11, s = m2 & 2047;
                float* o = out + (((size_t)(b * NH + h) * SS) + s) * HD + d;
                *(float2*)o = make_float2(acc[mt][nt][2] + bx, acc[mt][nt][3] + by);
            }
        }
    }
}

// ---------------------------------------------------------------------------
// Flash attention (FFMA): one query row per thread, 128 rows per block.
// ---------------------------------------------------------------------------
__global__ __launch_bounds__(128) void flash_kernel()
{
    const int bh   = blockIdx.y;          // b*NH + h
    const int b    = bh >> 4;
    const int h    = bh & 15;
    const int qrow = blockIdx.x * 128 + threadIdx.x;

    __shared__ float4 Ks4[64 * 16];       // 64 keys x 64 dims
    __shared__ float4 Vs4[64 * 16];

    float qreg[64];
    {
        const float4* qp = (const float4*)(g_Q + ((size_t)bh * SS + qrow) * HD);
#pragma unroll
        for (int i = 0; i < 16; i++) {
            float4 t = qp[i];
            qreg[4 * i + 0] = t.x * 0.125f;
            qreg[4 * i + 1] = t.y * 0.125f;
            qreg[4 * i + 2] = t.z * 0.125f;
            qreg[4 * i + 3] = t.w * 0.125f;
        }
    }

    float accv[64];
#pragma unroll
    for (int d = 0; d < 64; d++) accv[d] = 0.0f;
    float m = -1e30f;
    float l = 0.0f;

    const float4* Kg = (const float4*)(g_K + (size_t)bh * SS * HD);
    const float4* Vg = (const float4*)(g_V + (size_t)bh * SS * HD);

    for (int kt = 0; kt < SS / 64; kt++) {
        const float4* Kt = Kg + (size_t)kt * 64 * 16;
        const float4* Vt = Vg + (size_t)kt * 64 * 16;
#pragma unroll
        for (int i = 0; i < 8; i++) {
            int idx = threadIdx.x + i * 128;
            Ks4[idx] = Kt[idx];
            Vs4[idx] = Vt[idx];
        }
        __syncthreads();

#pragma unroll 1
        for (int ch = 0; ch < 4; ch++) {
            float s[16];
#pragma unroll
            for (int jj = 0; jj < 16; jj++) {
                const float4* kp = Ks4 + (ch * 16 + jj) * 16;
                float a = 0.0f;
#pragma unroll
                for (int d = 0; d < 16; d++) {
                    float4 kv = kp[d];
                    a += qreg[4 * d + 0] * kv.x;
                    a += qreg[4 * d + 1] * kv.y;
                    a += qreg[4 * d + 2] * kv.z;
                    a += qreg[4 * d + 3] * kv.w;
                }
                s[jj] = fminf(fmaxf(a, -10000.0f), 10000.0f);
            }
            float cmax = m;
#pragma unroll
            for (int jj = 0; jj < 16; jj++) cmax = fmaxf(cmax, s[jj]);
            float alpha = __expf(m - cmax);
            m = cmax;
            l *= alpha;
#pragma unroll
            for (int d = 0; d < 64; d++) accv[d] *= alpha;
#pragma unroll
            for (int jj = 0; jj < 16; jj++) {
                float p = __expf(s[jj] - m);
                l += p;
                const float4* vp = Vs4 + (ch * 16 + jj) * 16;
#pragma unroll
                for (int d = 0; d < 16; d++) {
                    float4 vv = vp[d];
                    accv[4 * d + 0] += p * vv.x;
                    accv[4 * d + 1] += p * vv.y;
                    accv[4 * d + 2] += p * vv.z;
                    accv[4 * d + 3] += p * vv.w;
                }
            }
        }
        __syncthreads();
    }

    const float inv = 1.0f / l;
    float4* op = (float4*)(g_ctx + ((size_t)(b * SS + qrow)) * HH + h * HD);
#pragma unroll
    for (int d = 0; d < 16; d++) {
        float4 o;
        o.x = accv[4 * d + 0] * inv;
        o.y = accv[4 * d + 1] * inv;
        o.z = accv[4 * d + 2] * inv;
        o.w = accv[4 * d + 3] * inv;
        op[d] = o;
    }
}

// ---------------------------------------------------------------------------
// O projection (tensor core): y = ctx @ Wo + bo + x
// ---------------------------------------------------------------------------
__global__ __launch_bounds__(256, 1) void oproj_gemm_kernel(
    const float* __restrict__ x,
    const float* __restrict__ Wo, const float* __restrict__ bo)
{
    __shared__ __align__(16) float As[128 * AS_ST];
    __shared__ __align__(16) float Bs[32 * BS_ST];

    float acc[4][4][4];
    gemm128_mainloop(g_ctx, Wo, As, Bs, acc);

    const int tid  = threadIdx.x;
    const int warp = tid >> 5;
    const int lane = tid & 31;
    const int gid  = lane >> 2;
    const int t4   = lane & 3;
    const int warp_m = (warp >> 2) * 64;
    const int warp_n = (warp & 3) * 32;
    const int m0 = blockIdx.y * 128;
    const int n0 = blockIdx.x * 128;

#pragma unroll
    for (int mt = 0; mt < 4; mt++) {
        const int mrow = m0 + warp_m + mt * 16 + gid;
#pragma unroll
        for (int nt = 0; nt < 4; nt++) {
            const int n = n0 + warp_n + nt * 8 + t4 * 2;
            const float bx = bo[n], by = bo[n + 1];
            {
                const float* xr = x + (size_t)mrow * HH + n;
                float* yo = g_y + (size_t)mrow * HH + n;
                *(float2*)yo = make_float2(acc[mt][nt][0] + bx + xr[0],
                                           acc[mt][nt][1] + by + xr[1]);
            }
            {
                const float* xr = x + (size_t)(mrow + 8) * HH + n;
                float* yo = g_y + (size_t)(mrow + 8) * HH + n;
                *(float2*)yo = make_float2(acc[mt][nt][2] + bx + xr[0],
                                           acc[mt][nt][3] + by + xr[1]);
            }
        }
    }
}

// ---------------------------------------------------------------------------
// LayerNorm over last dim (1024), one block per row.
// ---------------------------------------------------------------------------
__global__ __launch_bounds__(256) void ln_kernel(
    const float* __restrict__ gamma, const float* __restrict__ beta,
    float* __restrict__ out)
{
    __shared__ float red[256];
    const int row = blockIdx.x;
    const int tid = threadIdx.x;

    const float4* yp = (const float4*)(g_y + (size_t)row * HH);
    float4 v = yp[tid];

    float s = v.x + v.y + v.z + v.w;
    red[tid] = s;
    __syncthreads();
    for (int off = 128; off > 0; off >>= 1) {
        if (tid < off) red[tid] += red[tid + off];
        __syncthreads();
    }
    const float mu = red[0] * (1.0f / HH);
    __syncthreads();

    float dx = v.x - mu, dy = v.y - mu, dz = v.z - mu, dw = v.w - mu;
    red[tid] = dx * dx + dy * dy + dz * dz + dw * dw;
    __syncthreads();
    for (int off = 128; off > 0; off >>= 1) {
        if (tid < off) red[tid] += red[tid + off];
        __syncthreads();
    }
    const float var = red[0] * (1.0f / HH);
    const float inv = rsqrtf(var + 1e-5f);

    const float4 g  = ((const float4*)gamma)[tid];
    const float4 be = ((const float4*)beta)[tid];
    float4 o;
    o.x = dx * inv * g.x + be.x;
    o.y = dy * inv * g.y + be.y;
    o.z = dz * inv * g.z + be.z;
    o.w = dw * inv * g.w + be.w;
    ((float4*)out)[(size_t)row * (HH / 4) + tid] = o;
}

// ---------------------------------------------------------------------------
extern "C" void kernel_launch(void* const* d_in, const int* in_sizes, int n_in,
                              void* d_out, int out_size)
{
    (void)in_sizes; (void)n_in; (void)out_size;
    const float* x  = (const float*)d_in[0];
    const float* Wq = (const float*)d_in[1];
    const float* bq = (const float*)d_in[2];
    const float* Wk = (const float*)d_in[3];
    const float* bk = (const float*)d_in[4];
    const float* Wv = (const float*)d_in[5];
    const float* bv = (const float*)d_in[6];
    const float* Wo = (const float*)d_in[7];
    const float* bo = (const float*)d_in[8];
    const float* ga = (const float*)d_in[9];
    const float* be = (const float*)d_in[10];
    float* out = (float*)d_out;

    dim3 gq(HH / 128, MTOT / 128, 3);
    qkv_gemm_kernel<<<gq, 256>>>(x, Wq, bq, Wk, bk, Wv, bv);

    dim3 gf(SS / 128, BB * NH);
    flash_kernel<<<gf, 128>>>();

    dim3 go(HH / 128, MTOT / 128);
    oproj_gemm_kernel<<<go, 256>>>(x, Wo, bo);

    ln_kernel<<<MTOT, 256>>>(ga, be, out);
}

// round 6
// speedup vs baseline: 3.2237x; 2.8796x over previous
#include <cuda_runtime.h>
#include <stdint.h>
#include <math.h>

// Problem constants
static constexpr int BB   = 2;
static constexpr int SS   = 2048;
static constexpr int HH   = 1024;
static constexpr int NH   = 16;
static constexpr int HD   = 64;
static constexpr int MTOT = BB * SS;  // 4096 rows

// Scratch (static device globals; no dynamic allocation allowed)
__device__ float g_Q[(size_t)BB * NH * SS * HD];   // [bh][s][d]
__device__ float g_K[(size_t)BB * NH * SS * HD];
__device__ float g_V[(size_t)BB * NH * SS * HD];
__device__ float g_ctx[(size_t)MTOT * HH];         // row-major (b*S+s, H)
__device__ float g_y[(size_t)MTOT * HH];           // pre-LN: ctx@Wo + bo + x

// ---------------------------------------------------------------------------
// tf32 helpers
// ---------------------------------------------------------------------------
__device__ __forceinline__ uint32_t f2tf(float x) {
    uint32_t r;
    asm("cvt.rna.tf32.f32 %0, %1;" : "=r"(r) : "f"(x));
    return r;
}

__device__ __forceinline__ void mma8(float c[4], const uint32_t a[4], const uint32_t b[2]) {
    asm volatile(
        "mma.sync.aligned.m16n8k8.row.col.f32.tf32.tf32.f32 "
        "{%0,%1,%2,%3}, {%4,%5,%6,%7}, {%8,%9}, {%0,%1,%2,%3};"
        : "+f"(c[0]), "+f"(c[1]), "+f"(c[2]), "+f"(c[3])
        : "r"(a[0]), "r"(a[1]), "r"(a[2]), "r"(a[3]), "r"(b[0]), "r"(b[1]));
}

// ---------------------------------------------------------------------------
// 128x128x1024 tf32 mma mainloop (single-pass). 256 threads, 8 warps (2m x 4n),
// warp tile 64x32, mma tile m16n8k8.
// ---------------------------------------------------------------------------
static constexpr int AS_ST = 36;
static constexpr int BS_ST = 136;

__device__ __forceinline__ void gemm128_mainloop(
    const float* __restrict__ A, const float* __restrict__ B,
    float* As, float* Bs, float acc[4][4][4])
{
    const int tid  = threadIdx.x;
    const int m0   = blockIdx.y * 128;
    const int n0   = blockIdx.x * 128;
    const int warp = tid >> 5;
    const int lane = tid & 31;
    const int gid  = lane >> 2;
    const int t4   = lane & 3;
    const int warp_m = (warp >> 2) * 64;
    const int warp_n = (warp & 3) * 32;

    const int arow = tid >> 3;    // 0..31
    const int ac4  = tid & 7;     // 0..7
    const int brow = tid >> 5;    // 0..7
    const int bc4  = tid & 31;    // 0..31

#pragma unroll
    for (int mt = 0; mt < 4; mt++)
#pragma unroll
        for (int nt = 0; nt < 4; nt++)
#pragma unroll
            for (int r = 0; r < 4; r++) acc[mt][nt][r] = 0.0f;

    const float* ag = A + (size_t)(m0 + arow) * HH + ac4 * 4;
    const float* bg = B + (size_t)brow * HH + n0 + bc4 * 4;

    float4 aR[4], bR[4];
#pragma unroll
    for (int r = 0; r < 4; r++) {
        aR[r] = *(const float4*)(ag + (size_t)(32 * r) * HH);
        bR[r] = *(const float4*)(bg + (size_t)(8 * r) * HH);
    }

    for (int k0 = 0; k0 < HH; k0 += 32) {
#pragma unroll
        for (int r = 0; r < 4; r++) {
            *(float4*)&As[(arow + 32 * r) * AS_ST + ac4 * 4] = aR[r];
            *(float4*)&Bs[(brow + 8 * r) * BS_ST + bc4 * 4]  = bR[r];
        }
        __syncthreads();

        if (k0 + 32 < HH) {
            const float* ag2 = ag + (k0 + 32);
            const float* bg2 = bg + (size_t)(k0 + 32) * HH;
#pragma unroll
            for (int r = 0; r < 4; r++) {
                aR[r] = *(const float4*)(ag2 + (size_t)(32 * r) * HH);
                bR[r] = *(const float4*)(bg2 + (size_t)(8 * r) * HH);
            }
        }

#pragma unroll
        for (int ks = 0; ks < 4; ks++) {
            uint32_t Af[4][4];
#pragma unroll
            for (int mt = 0; mt < 4; mt++) {
                int base = (warp_m + mt * 16 + gid) * AS_ST + ks * 8 + t4;
                Af[mt][0] = f2tf(As[base]);
                Af[mt][1] = f2tf(As[base + 8 * AS_ST]);
                Af[mt][2] = f2tf(As[base + 4]);
                Af[mt][3] = f2tf(As[base + 8 * AS_ST + 4]);
            }
            uint32_t Bf[4][2];
#pragma unroll
            for (int nt = 0; nt < 4; nt++) {
                int cb = (ks * 8 + t4) * BS_ST + warp_n + nt * 8 + gid;
                Bf[nt][0] = f2tf(Bs[cb]);
                Bf[nt][1] = f2tf(Bs[cb + 4 * BS_ST]);
            }
#pragma unroll
            for (int mt = 0; mt < 4; mt++)
#pragma unroll
                for (int nt = 0; nt < 4; nt++)
                    mma8(acc[mt][nt], Af[mt], Bf[nt]);
        }
        __syncthreads();
    }
}

// ---------------------------------------------------------------------------
// QKV GEMM (tensor core): out = x @ W + b, scattered head-major.
// ---------------------------------------------------------------------------
__global__ __launch_bounds__(256, 1) void qkv_gemm_kernel(
    const float* __restrict__ x,
    const float* __restrict__ Wq, const float* __restrict__ bq,
    const float* __restrict__ Wk, const float* __restrict__ bk,
    const float* __restrict__ Wv, const float* __restrict__ bv)
{
    const int mat = blockIdx.z;
    const float* W    = (mat == 0) ? Wq : (mat == 1 ? Wk : Wv);
    const float* bias = (mat == 0) ? bq : (mat == 1 ? bk : bv);
    float* out        = (mat == 0) ? g_Q : (mat == 1 ? g_K : g_V);

    __shared__ __align__(16) float As[128 * AS_ST];
    __shared__ __align__(16) float Bs[32 * BS_ST];

    float acc[4][4][4];
    gemm128_mainloop(x, W, As, Bs, acc);

    const int tid  = threadIdx.x;
    const int warp = tid >> 5;
    const int lane = tid & 31;
    const int gid  = lane >> 2;
    const int t4   = lane & 3;
    const int warp_m = (warp >> 2) * 64;
    const int warp_n = (warp & 3) * 32;
    const int m0 = blockIdx.y * 128;
    const int n0 = blockIdx.x * 128;

#pragma unroll
    for (int mt = 0; mt < 4; mt++) {
        const int mrow = m0 + warp_m + mt * 16 + gid;
#pragma unroll
        for (int nt = 0; nt < 4; nt++) {
            const int n = n0 + warp_n + nt * 8 + t4 * 2;
            const int h = n >> 6;
            const int d = n & 63;
            const float bx = bias[n], by = bias[n + 1];
            {
                int b = mrow >> 11, s = mrow & 2047;
                float* o = out + (((size_t)(b * NH + h) * SS) + s) * HD + d;
                *(float2*)o = make_float2(acc[mt][nt][0] + bx, acc[mt][nt][1] + by);
            }
            {
                int m2 = mrow + 8;
                int b = m2 >> 11, s = m2 & 2047;
                float* o = out + (((size_t)(b * NH + h) * SS) + s) * HD + d;
                *(float2*)o = make_float2(acc[mt][nt][2] + bx, acc[mt][nt][3] + by);
            }
        }
    }
}

// ---------------------------------------------------------------------------
// Tensor-core flash attention (FA2 style, m16n8k8 tf32).
// Block: 256 threads (8 warps) -> 128 q rows; warp w owns rows [w*16, w*16+16).
// K/V tiles: 64 keys, staged into smem PRE-CONVERTED to tf32.
// smem budget: max(Q stage 128*68, K+V 2*64*68) = 8704 words = 34 KB.
// ---------------------------------------------------------------------------
static constexpr int KV_ST = 68;   // row stride (64 + 4 pad)

__global__ __launch_bounds__(256, 1) void flash_tc_kernel()
{
    __shared__ __align__(16) uint32_t smu[8704];

    const int bh  = blockIdx.y;     // b*NH + h
    const int b   = bh >> 4;
    const int h   = bh & 15;
    const int q0  = blockIdx.x * 128;
    const int tid = threadIdx.x;
    const int warp = tid >> 5;
    const int lane = tid & 31;
    const int gid  = lane >> 2;
    const int t4   = lane & 3;
    const unsigned F = 0xFFFFFFFFu;

    // ---- Stage Q (128 x 64) as floats, extract tf32 A-frags (pre-scaled) ----
    {
        float* Qs = (float*)smu;
        const float4* Qg = (const float4*)(g_Q + ((size_t)bh * SS + q0) * HD);
#pragma unroll
        for (int i = 0; i < 8; i++) {
            int idx = tid + i * 256;        // 0..2047 float4s
            int row = idx >> 4, c4 = idx & 15;
            *(float4*)&Qs[row * KV_ST + c4 * 4] = Qg[idx];
        }
    }
    __syncthreads();

    uint32_t Qa[8][4];
    {
        const float* Qs = (const float*)smu;
        const int r0 = (warp * 16 + gid) * KV_ST;
        const int r1 = r0 + 8 * KV_ST;
#pragma unroll
        for (int ks = 0; ks < 8; ks++) {
            int c = ks * 8 + t4;
            Qa[ks][0] = f2tf(Qs[r0 + c] * 0.125f);
            Qa[ks][1] = f2tf(Qs[r1 + c] * 0.125f);
            Qa[ks][2] = f2tf(Qs[r0 + c + 4] * 0.125f);
            Qa[ks][3] = f2tf(Qs[r1 + c + 4] * 0.125f);
        }
    }
    __syncthreads();

    float Oc[8][4];
#pragma unroll
    for (int dt = 0; dt < 8; dt++)
#pragma unroll
        for (int r = 0; r < 4; r++) Oc[dt][r] = 0.0f;
    float m0r = -1e30f, m1r = -1e30f;
    float l0r = 0.0f,   l1r = 0.0f;

    uint32_t* Ks = smu;                 // 64*68 words
    uint32_t* Vs = smu + 64 * KV_ST;

    const float4* Kg = (const float4*)(g_K + (size_t)bh * SS * HD);
    const float4* Vg = (const float4*)(g_V + (size_t)bh * SS * HD);

    for (int kt = 0; kt < SS / 64; kt++) {
        // ---- stage K/V tile, converting to tf32 bits ----
#pragma unroll
        for (int i = 0; i < 4; i++) {
            int idx = tid + i * 256;        // 0..1023 float4s
            int row = idx >> 4, c4 = idx & 15;
            float4 kv = Kg[kt * 1024 + idx];
            float4 vv = Vg[kt * 1024 + idx];
            uint32_t* kd = &Ks[row * KV_ST + c4 * 4];
            uint32_t* vd = &Vs[row * KV_ST + c4 * 4];
            kd[0] = f2tf(kv.x); kd[1] = f2tf(kv.y); kd[2] = f2tf(kv.z); kd[3] = f2tf(kv.w);
            vd[0] = f2tf(vv.x); vd[1] = f2tf(vv.y); vd[2] = f2tf(vv.z); vd[3] = f2tf(vv.w);
        }
        __syncthreads();

        // ---- S = Q K^T (pre-scaled), 8 key n-tiles ----
        float S[8][4];
#pragma unroll
        for (int nt = 0; nt < 8; nt++) {
            S[nt][0] = S[nt][1] = S[nt][2] = S[nt][3] = 0.0f;
            const uint32_t* kr = &Ks[(nt * 8 + gid) * KV_ST + t4];
#pragma unroll
            for (int ks = 0; ks < 8; ks++) {
                uint32_t bfr[2];
                bfr[0] = kr[ks * 8];
                bfr[1] = kr[ks * 8 + 4];
                mma8(S[nt], Qa[ks], bfr);
            }
        }

        // ---- clip + online softmax (rows gid / gid+8) ----
        float tmax0 = -1e30f, tmax1 = -1e30f;
#pragma unroll
        for (int nt = 0; nt < 8; nt++) {
#pragma unroll
            for (int r = 0; r < 4; r++)
                S[nt][r] = fminf(fmaxf(S[nt][r], -10000.0f), 10000.0f);
            tmax0 = fmaxf(tmax0, fmaxf(S[nt][0], S[nt][1]));
            tmax1 = fmaxf(tmax1, fmaxf(S[nt][2], S[nt][3]));
        }
        tmax0 = fmaxf(tmax0, __shfl_xor_sync(F, tmax0, 1));
        tmax0 = fmaxf(tmax0, __shfl_xor_sync(F, tmax0, 2));
        tmax1 = fmaxf(tmax1, __shfl_xor_sync(F, tmax1, 1));
        tmax1 = fmaxf(tmax1, __shfl_xor_sync(F, tmax1, 2));

        float nm0 = fmaxf(m0r, tmax0);
        float nm1 = fmaxf(m1r, tmax1);
        float al0 = __expf(m0r - nm0);
        float al1 = __expf(m1r - nm1);
        m0r = nm0; m1r = nm1;

        float sum0 = 0.0f, sum1 = 0.0f;
#pragma unroll
        for (int nt = 0; nt < 8; nt++) {
            S[nt][0] = __expf(S[nt][0] - nm0);
            S[nt][1] = __expf(S[nt][1] - nm0);
            S[nt][2] = __expf(S[nt][2] - nm1);
            S[nt][3] = __expf(S[nt][3] - nm1);
            sum0 += S[nt][0] + S[nt][1];
            sum1 += S[nt][2] + S[nt][3];
        }
        sum0 += __shfl_xor_sync(F, sum0, 1);
        sum0 += __shfl_xor_sync(F, sum0, 2);
        sum1 += __shfl_xor_sync(F, sum1, 1);
        sum1 += __shfl_xor_sync(F, sum1, 2);
        l0r = l0r * al0 + sum0;
        l1r = l1r * al1 + sum1;

#pragma unroll
        for (int dt = 0; dt < 8; dt++) {
            Oc[dt][0] *= al0; Oc[dt][1] *= al0;
            Oc[dt][2] *= al1; Oc[dt][3] *= al1;
        }

        // ---- ctx += P V : per 8-key chunk ks, gather P into A-frag via shfl ----
        const int src0 = (lane & ~3) | (t4 >> 1);
        const int src2 = src0 + 2;
        const bool odd = (t4 & 1);
#pragma unroll
        for (int ks = 0; ks < 8; ks++) {
            float p00 = __shfl_sync(F, S[ks][0], src0);
            float p01 = __shfl_sync(F, S[ks][1], src0);
            float p10 = __shfl_sync(F, S[ks][2], src0);
            float p11 = __shfl_sync(F, S[ks][3], src0);
            float q00 = __shfl_sync(F, S[ks][0], src2);
            float q01 = __shfl_sync(F, S[ks][1], src2);
            float q10 = __shfl_sync(F, S[ks][2], src2);
            float q11 = __shfl_sync(F, S[ks][3], src2);
            uint32_t Pa[4];
            Pa[0] = f2tf(odd ? p01 : p00);
            Pa[1] = f2tf(odd ? p11 : p10);
            Pa[2] = f2tf(odd ? q01 : q00);
            Pa[3] = f2tf(odd ? q11 : q10);
            const uint32_t* vr = &Vs[(ks * 8 + t4) * KV_ST + gid];
#pragma unroll
            for (int dt = 0; dt < 8; dt++) {
                uint32_t bb[2];
                bb[0] = vr[dt * 8];
                bb[1] = vr[dt * 8 + 4 * KV_ST];
                mma8(Oc[dt], Pa, bb);
            }
        }
        __syncthreads();
    }

    // ---- epilogue: normalize, write ctx row-major with head offset ----
    const float inv0 = 1.0f / l0r;
    const float inv1 = 1.0f / l1r;
    const int srow = q0 + warp * 16 + gid;
    float* out0 = g_ctx + ((size_t)(b * SS + srow)) * HH + h * HD;
    float* out1 = out0 + (size_t)8 * HH;
#pragma unroll
    for (int dt = 0; dt < 8; dt++) {
        int c = dt * 8 + t4 * 2;
        *(float2*)(out0 + c) = make_float2(Oc[dt][0] * inv0, Oc[dt][1] * inv0);
        *(float2*)(out1 + c) = make_float2(Oc[dt][2] * inv1, Oc[dt][3] * inv1);
    }
}

// ---------------------------------------------------------------------------
// O projection (tensor core): y = ctx @ Wo + bo + x
// ---------------------------------------------------------------------------
__global__ __launch_bounds__(256, 1) void oproj_gemm_kernel(
    const float* __restrict__ x,
    const float* __restrict__ Wo, const float* __restrict__ bo)
{
    __shared__ __align__(16) float As[128 * AS_ST];
    __shared__ __align__(16) float Bs[32 * BS_ST];

    float acc[4][4][4];
    gemm128_mainloop(g_ctx, Wo, As, Bs, acc);

    const int tid  = threadIdx.x;
    const int warp = tid >> 5;
    const int lane = tid & 31;
    const int gid  = lane >> 2;
    const int t4   = lane & 3;
    const int warp_m = (warp >> 2) * 64;
    const int warp_n = (warp & 3) * 32;
    const int m0 = blockIdx.y * 128;
    const int n0 = blockIdx.x * 128;

#pragma unroll
    for (int mt = 0; mt < 4; mt++) {
        const int mrow = m0 + warp_m + mt * 16 + gid;
#pragma unroll
        for (int nt = 0; nt < 4; nt++) {
            const int n = n0 + warp_n + nt * 8 + t4 * 2;
            const float bx = bo[n], by = bo[n + 1];
            {
                const float* xr = x + (size_t)mrow * HH + n;
                float* yo = g_y + (size_t)mrow * HH + n;
                *(float2*)yo = make_float2(acc[mt][nt][0] + bx + xr[0],
                                           acc[mt][nt][1] + by + xr[1]);
            }
            {
                const float* xr = x + (size_t)(mrow + 8) * HH + n;
                float* yo = g_y + (size_t)(mrow + 8) * HH + n;
                *(float2*)yo = make_float2(acc[mt][nt][2] + bx + xr[0],
                                           acc[mt][nt][3] + by + xr[1]);
            }
        }
    }
}

// ---------------------------------------------------------------------------
// LayerNorm over last dim (1024), one block per row.
// ---------------------------------------------------------------------------
__global__ __launch_bounds__(256) void ln_kernel(
    const float* __restrict__ gamma, const float* __restrict__ beta,
    float* __restrict__ out)
{
    __shared__ float red[256];
    const int row = blockIdx.x;
    const int tid = threadIdx.x;

    const float4* yp = (const float4*)(g_y + (size_t)row * HH);
    float4 v = yp[tid];

    float s = v.x + v.y + v.z + v.w;
    red[tid] = s;
    __syncthreads();
    for (int off = 128; off > 0; off >>= 1) {
        if (tid < off) red[tid] += red[tid + off];
        __syncthreads();
    }
    const float mu = red[0] * (1.0f / HH);
    __syncthreads();

    float dx = v.x - mu, dy = v.y - mu, dz = v.z - mu, dw = v.w - mu;
    red[tid] = dx * dx + dy * dy + dz * dz + dw * dw;
    __syncthreads();
    for (int off = 128; off > 0; off >>= 1) {
        if (tid < off) red[tid] += red[tid + off];
        __syncthreads();
    }
    const float var = red[0] * (1.0f / HH);
    const float inv = rsqrtf(var + 1e-5f);

    const float4 g  = ((const float4*)gamma)[tid];
    const float4 be = ((const float4*)beta)[tid];
    float4 o;
    o.x = dx * inv * g.x + be.x;
    o.y = dy * inv * g.y + be.y;
    o.z = dz * inv * g.z + be.z;
    o.w = dw * inv * g.w + be.w;
    ((float4*)out)[(size_t)row * (HH / 4) + tid] = o;
}

// ---------------------------------------------------------------------------
extern "C" void kernel_launch(void* const* d_in, const int* in_sizes, int n_in,
                              void* d_out, int out_size)
{
    (void)in_sizes; (void)n_in; (void)out_size;
    const float* x  = (const float*)d_in[0];
    const float* Wq = (const float*)d_in[1];
    const float* bq = (const float*)d_in[2];
    const float* Wk = (const float*)d_in[3];
    const float* bk = (const float*)d_in[4];
    const float* Wv = (const float*)d_in[5];
    const float* bv = (const float*)d_in[6];
    const float* Wo = (const float*)d_in[7];
    const float* bo = (const float*)d_in[8];
    const float* ga = (const float*)d_in[9];
    const float* be = (const float*)d_in[10];
    float* out = (float*)d_out;

    dim3 gq(HH / 128, MTOT / 128, 3);
    qkv_gemm_kernel<<<gq, 256>>>(x, Wq, bq, Wk, bk, Wv, bv);

    dim3 gf(SS / 128, BB * NH);
    flash_tc_kernel<<<gf, 256>>>();

    dim3 go(HH / 128, MTOT / 128);
    oproj_gemm_kernel<<<go, 256>>>(x, Wo, bo);

    ln_kernel<<<MTOT, 256>>>(ga, be, out);
}

// round 7
// speedup vs baseline: 5.3462x; 1.6584x over previous
#include <cuda_runtime.h>
#include <cuda_fp16.h>
#include <stdint.h>
#include <math.h>

// Problem constants
static constexpr int BB   = 2;
static constexpr int SS   = 2048;
static constexpr int HH   = 1024;
static constexpr int NH   = 16;
static constexpr int HD   = 64;
static constexpr int MTOT = BB * SS;  // 4096 rows

// Scratch (static device globals)
__device__ __half g_Q[(size_t)BB * NH * SS * HD];   // [bh][s][d], pre-scaled 0.125
__device__ __half g_K[(size_t)BB * NH * SS * HD];
__device__ __half g_V[(size_t)BB * NH * SS * HD];
__device__ float  g_ctx[(size_t)MTOT * HH];         // row-major (b*S+s, H)
__device__ float  g_y[(size_t)MTOT * HH];           // pre-LN

// ---------------------------------------------------------------------------
// fp16 helpers
// ---------------------------------------------------------------------------
__device__ __forceinline__ uint32_t pack2h(float lo, float hi) {
    uint32_t r;
    asm("cvt.rn.f16x2.f32 %0, %1, %2;" : "=r"(r) : "f"(hi), "f"(lo));
    return r;
}
__device__ __forceinline__ uint32_t pack_hh(const __half* p0, const __half* p1) {
    uint32_t lo = *(const uint16_t*)p0;
    uint32_t hi = *(const uint16_t*)p1;
    return lo | (hi << 16);
}
__device__ __forceinline__ void mma16(float c[4], const uint32_t a[4], const uint32_t b[2]) {
    asm volatile(
        "mma.sync.aligned.m16n8k16.row.col.f32.f16.f16.f32 "
        "{%0,%1,%2,%3}, {%4,%5,%6,%7}, {%8,%9}, {%0,%1,%2,%3};"
        : "+f"(c[0]), "+f"(c[1]), "+f"(c[2]), "+f"(c[3])
        : "r"(a[0]), "r"(a[1]), "r"(a[2]), "r"(a[3]), "r"(b[0]), "r"(b[1]));
}

// ---------------------------------------------------------------------------
// 128x128x1024 fp16 mma mainloop. 256 threads, 8 warps (2m x 4n),
// warp tile 64x32, mma m16n8k16, BK=32 (2 k16 steps / tile).
// As[128][40] halfs row-major (m, k);  Bs[32][136] halfs (k, n).
// ---------------------------------------------------------------------------
static constexpr int AS_ST = 40;    // halfs
static constexpr int BS_ST = 136;   // halfs

__device__ __forceinline__ void gemm128_mainloop(
    const float* __restrict__ A, const float* __restrict__ B,
    __half* As, __half* Bs, float acc[4][4][4])
{
    const int tid  = threadIdx.x;
    const int m0   = blockIdx.y * 128;
    const int n0   = blockIdx.x * 128;
    const int warp = tid >> 5;
    const int lane = tid & 31;
    const int gid  = lane >> 2;
    const int t4   = lane & 3;
    const int warp_m = (warp >> 2) * 64;
    const int warp_n = (warp & 3) * 32;

    const int arow = tid >> 3;    // 0..31 (A rows, +32*r)
    const int ac4  = tid & 7;     // 0..7  (A k-groups of 4)
    const int brow = tid >> 5;    // 0..7  (B k rows, +8*r)
    const int bc4  = tid & 31;    // 0..31 (B n-groups of 4)

#pragma unroll
    for (int mt = 0; mt < 4; mt++)
#pragma unroll
        for (int nt = 0; nt < 4; nt++)
#pragma unroll
            for (int r = 0; r < 4; r++) acc[mt][nt][r] = 0.0f;

    const float* ag = A + (size_t)(m0 + arow) * HH + ac4 * 4;
    const float* bg = B + (size_t)brow * HH + n0 + bc4 * 4;

    float4 aR[4], bR[4];
#pragma unroll
    for (int r = 0; r < 4; r++) {
        aR[r] = *(const float4*)(ag + (size_t)(32 * r) * HH);
        bR[r] = *(const float4*)(bg + (size_t)(8 * r) * HH);
    }

    for (int k0 = 0; k0 < HH; k0 += 32) {
        // stage to smem (convert fp32 -> fp16)
#pragma unroll
        for (int r = 0; r < 4; r++) {
            uint2 av; av.x = pack2h(aR[r].x, aR[r].y); av.y = pack2h(aR[r].z, aR[r].w);
            uint2 bv; bv.x = pack2h(bR[r].x, bR[r].y); bv.y = pack2h(bR[r].z, bR[r].w);
            *(uint2*)&As[(arow + 32 * r) * AS_ST + ac4 * 4] = av;
            *(uint2*)&Bs[(brow + 8 * r) * BS_ST + bc4 * 4]  = bv;
        }
        __syncthreads();

        if (k0 + 32 < HH) {
            const float* ag2 = ag + (k0 + 32);
            const float* bg2 = bg + (size_t)(k0 + 32) * HH;
#pragma unroll
            for (int r = 0; r < 4; r++) {
                aR[r] = *(const float4*)(ag2 + (size_t)(32 * r) * HH);
                bR[r] = *(const float4*)(bg2 + (size_t)(8 * r) * HH);
            }
        }

#pragma unroll
        for (int ks = 0; ks < 2; ks++) {
            uint32_t Af[4][4];
#pragma unroll
            for (int mt = 0; mt < 4; mt++) {
                const __half* ap = &As[(warp_m + mt * 16 + gid) * AS_ST + ks * 16 + t4 * 2];
                Af[mt][0] = *(const uint32_t*)ap;
                Af[mt][1] = *(const uint32_t*)(ap + 8 * AS_ST);
                Af[mt][2] = *(const uint32_t*)(ap + 8);
                Af[mt][3] = *(const uint32_t*)(ap + 8 * AS_ST + 8);
            }
            uint32_t Bf[4][2];
#pragma unroll
            for (int nt = 0; nt < 4; nt++) {
                const __half* bp = &Bs[(ks * 16 + 2 * t4) * BS_ST + warp_n + nt * 8 + gid];
                Bf[nt][0] = pack_hh(bp, bp + BS_ST);
                Bf[nt][1] = pack_hh(bp + 8 * BS_ST, bp + 9 * BS_ST);
            }
#pragma unroll
            for (int mt = 0; mt < 4; mt++)
#pragma unroll
                for (int nt = 0; nt < 4; nt++)
                    mma16(acc[mt][nt], Af[mt], Bf[nt]);
        }
        __syncthreads();
    }
}

// ---------------------------------------------------------------------------
// QKV GEMM: out = x @ W + b  (Q additionally scaled by 0.125), fp16 out,
// scattered head-major. blockIdx.z selects Q/K/V.
// ---------------------------------------------------------------------------
__global__ __launch_bounds__(256, 1) void qkv_gemm_kernel(
    const float* __restrict__ x,
    const float* __restrict__ Wq, const float* __restrict__ bq,
    const float* __restrict__ Wk, const float* __restrict__ bk,
    const float* __restrict__ Wv, const float* __restrict__ bv)
{
    const int mat = blockIdx.z;
    const float* W    = (mat == 0) ? Wq : (mat == 1 ? Wk : Wv);
    const float* bias = (mat == 0) ? bq : (mat == 1 ? bk : bv);
    __half* out       = (mat == 0) ? g_Q : (mat == 1 ? g_K : g_V);
    const float osc   = (mat == 0) ? 0.125f : 1.0f;

    __shared__ __align__(16) __half As[128 * AS_ST];
    __shared__ __align__(16) __half Bs[32 * BS_ST];

    float acc[4][4][4];
    gemm128_mainloop(x, W, As, Bs, acc);

    const int tid  = threadIdx.x;
    const int warp = tid >> 5;
    const int lane = tid & 31;
    const int gid  = lane >> 2;
    const int t4   = lane & 3;
    const int warp_m = (warp >> 2) * 64;
    const int warp_n = (warp & 3) * 32;
    const int m0 = blockIdx.y * 128;
    const int n0 = blockIdx.x * 128;

#pragma unroll
    for (int mt = 0; mt < 4; mt++) {
        const int mrow = m0 + warp_m + mt * 16 + gid;
#pragma unroll
        for (int nt = 0; nt < 4; nt++) {
            const int n = n0 + warp_n + nt * 8 + t4 * 2;
            const int h = n >> 6;
            const int d = n & 63;
            const float bx = bias[n], by = bias[n + 1];
            {
                int b = mrow >> 11, s = mrow & 2047;
                __half* o = out + (((size_t)(b * NH + h) * SS) + s) * HD + d;
                *(uint32_t*)o = pack2h((acc[mt][nt][0] + bx) * osc,
                                       (acc[mt][nt][1] + by) * osc);
            }
            {
                int m2 = mrow + 8;
                int b = m2 >> 11, s = m2 & 2047;
                __half* o = out + (((size_t)(b * NH + h) * SS) + s) * HD + d;
                *(uint32_t*)o = pack2h((acc[mt][nt][2] + bx) * osc,
                                       (acc[mt][nt][3] + by) * osc);
            }
        }
    }
}

// ---------------------------------------------------------------------------
// Tensor-core flash attention, fp16 m16n8k16.
// 256 threads (8 warps) -> 128 q rows; warp w owns rows [w*16, w*16+16).
// K/V tiles: 64 keys. smem 18 KB -> 2 CTAs/SM.
// P->A-frag needs NO shuffles (fp16 C-frag == A-frag layout).
// ---------------------------------------------------------------------------
static constexpr int FK_ST = 72;   // halfs per row (64 + 8 pad)

__global__ __launch_bounds__(256, 2) void flash_tc_kernel()
{
    __shared__ __align__(16) __half sm[9216];   // 18 KB

    const int bh  = blockIdx.y;     // b*NH + h
    const int b   = bh >> 4;
    const int h   = bh & 15;
    const int q0  = blockIdx.x * 128;
    const int tid = threadIdx.x;
    const int warp = tid >> 5;
    const int lane = tid & 31;
    const int gid  = lane >> 2;
    const int t4   = lane & 3;
    const unsigned F = 0xFFFFFFFFu;

    // ---- Stage Q (128 x 64 halfs, already scaled) ----
    {
        const uint2* Qg = (const uint2*)(g_Q + ((size_t)bh * SS + q0) * HD);
#pragma unroll
        for (int i = 0; i < 8; i++) {
            int idx = tid + i * 256;        // 0..2047 (4-half groups)
            int row = idx >> 4, c4 = idx & 15;
            *(uint2*)&sm[row * FK_ST + c4 * 4] = Qg[idx];
        }
    }
    __syncthreads();

    // ---- Extract Q A-frags: 4 k16 steps ----
    uint32_t Qa[4][4];
    {
        const int r0 = (warp * 16 + gid) * FK_ST;
#pragma unroll
        for (int ks = 0; ks < 4; ks++) {
            const __half* qp = &sm[r0 + ks * 16 + t4 * 2];
            Qa[ks][0] = *(const uint32_t*)qp;
            Qa[ks][1] = *(const uint32_t*)(qp + 8 * FK_ST);
            Qa[ks][2] = *(const uint32_t*)(qp + 8);
            Qa[ks][3] = *(const uint32_t*)(qp + 8 * FK_ST + 8);
        }
    }
    __syncthreads();

    float Oc[8][4];
#pragma unroll
    for (int dt = 0; dt < 8; dt++)
#pragma unroll
        for (int r = 0; r < 4; r++) Oc[dt][r] = 0.0f;
    float m0r = -1e30f, m1r = -1e30f;
    float l0r = 0.0f,   l1r = 0.0f;

    __half* Ks = sm;                 // 64*72
    __half* Vs = sm + 64 * FK_ST;

    const uint2* Kg = (const uint2*)(g_K + (size_t)bh * SS * HD);
    const uint2* Vg = (const uint2*)(g_V + (size_t)bh * SS * HD);

    for (int kt = 0; kt < SS / 64; kt++) {
        // ---- stage K/V tile (pure copies) ----
#pragma unroll
        for (int i = 0; i < 4; i++) {
            int idx = tid + i * 256;        // 0..1023
            int row = idx >> 4, c4 = idx & 15;
            *(uint2*)&Ks[row * FK_ST + c4 * 4] = Kg[kt * 1024 + idx];
            *(uint2*)&Vs[row * FK_ST + c4 * 4] = Vg[kt * 1024 + idx];
        }
        __syncthreads();

        // ---- S = Q K^T : 8 key n-tiles x 4 k16 steps ----
        float S[8][4];
#pragma unroll
        for (int nt = 0; nt < 8; nt++)
            S[nt][0] = S[nt][1] = S[nt][2] = S[nt][3] = 0.0f;
#pragma unroll
        for (int ks = 0; ks < 4; ks++) {
#pragma unroll
            for (int nt = 0; nt < 8; nt++) {
                const __half* kb = &Ks[(nt * 8 + gid) * FK_ST + ks * 16 + t4 * 2];
                uint32_t bb[2];
                bb[0] = *(const uint32_t*)kb;
                bb[1] = *(const uint32_t*)(kb + 8);
                mma16(S[nt], Qa[ks], bb);
            }
        }

        // ---- clip + online softmax (rows gid / gid+8) ----
        float tmax0 = -1e30f, tmax1 = -1e30f;
#pragma unroll
        for (int nt = 0; nt < 8; nt++) {
#pragma unroll
            for (int r = 0; r < 4; r++)
                S[nt][r] = fminf(fmaxf(S[nt][r], -10000.0f), 10000.0f);
            tmax0 = fmaxf(tmax0, fmaxf(S[nt][0], S[nt][1]));
            tmax1 = fmaxf(tmax1, fmaxf(S[nt][2], S[nt][3]));
        }
        tmax0 = fmaxf(tmax0, __shfl_xor_sync(F, tmax0, 1));
        tmax0 = fmaxf(tmax0, __shfl_xor_sync(F, tmax0, 2));
        tmax1 = fmaxf(tmax1, __shfl_xor_sync(F, tmax1, 1));
        tmax1 = fmaxf(tmax1, __shfl_xor_sync(F, tmax1, 2));

        float nm0 = fmaxf(m0r, tmax0);
        float nm1 = fmaxf(m1r, tmax1);
        float al0 = __expf(m0r - nm0);
        float al1 = __expf(m1r - nm1);
        m0r = nm0; m1r = nm1;

        float sum0 = 0.0f, sum1 = 0.0f;
#pragma unroll
        for (int nt = 0; nt < 8; nt++) {
            S[nt][0] = __expf(S[nt][0] - nm0);
            S[nt][1] = __expf(S[nt][1] - nm0);
            S[nt][2] = __expf(S[nt][2] - nm1);
            S[nt][3] = __expf(S[nt][3] - nm1);
            sum0 += S[nt][0] + S[nt][1];
            sum1 += S[nt][2] + S[nt][3];
        }
        sum0 += __shfl_xor_sync(F, sum0, 1);
        sum0 += __shfl_xor_sync(F, sum0, 2);
        sum1 += __shfl_xor_sync(F, sum1, 1);
        sum1 += __shfl_xor_sync(F, sum1, 2);
        l0r = l0r * al0 + sum0;
        l1r = l1r * al1 + sum1;

#pragma unroll
        for (int dt = 0; dt < 8; dt++) {
            Oc[dt][0] *= al0; Oc[dt][1] *= al0;
            Oc[dt][2] *= al1; Oc[dt][3] *= al1;
        }

        // ---- ctx += P V : C-frag -> A-frag directly (no shuffles) ----
#pragma unroll
        for (int ks = 0; ks < 4; ks++) {
            uint32_t Pa[4];
            Pa[0] = pack2h(S[2 * ks][0],     S[2 * ks][1]);
            Pa[1] = pack2h(S[2 * ks][2],     S[2 * ks][3]);
            Pa[2] = pack2h(S[2 * ks + 1][0], S[2 * ks + 1][1]);
            Pa[3] = pack2h(S[2 * ks + 1][2], S[2 * ks + 1][3]);
#pragma unroll
            for (int dt = 0; dt < 8; dt++) {
                const __half* vb = &Vs[(ks * 16 + 2 * t4) * FK_ST + dt * 8 + gid];
                uint32_t bb[2];
                bb[0] = pack_hh(vb,              vb + FK_ST);
                bb[1] = pack_hh(vb + 8 * FK_ST,  vb + 9 * FK_ST);
                mma16(Oc[dt], Pa, bb);
            }
        }
        __syncthreads();
    }

    // ---- epilogue: normalize, write ctx row-major with head offset ----
    const float inv0 = 1.0f / l0r;
    const float inv1 = 1.0f / l1r;
    const int srow = q0 + warp * 16 + gid;
    float* out0 = g_ctx + ((size_t)(b * SS + srow)) * HH + h * HD;
    float* out1 = out0 + (size_t)8 * HH;
#pragma unroll
    for (int dt = 0; dt < 8; dt++) {
        int c = dt * 8 + t4 * 2;
        *(float2*)(out0 + c) = make_float2(Oc[dt][0] * inv0, Oc[dt][1] * inv0);
        *(float2*)(out1 + c) = make_float2(Oc[dt][2] * inv1, Oc[dt][3] * inv1);
    }
}

// ---------------------------------------------------------------------------
// O projection: y = ctx @ Wo + bo + x
// ---------------------------------------------------------------------------
__global__ __launch_bounds__(256, 1) void oproj_gemm_kernel(
    const float* __restrict__ x,
    const float* __restrict__ Wo, const float* __restrict__ bo)
{
    __shared__ __align__(16) __half As[128 * AS_ST];
    __shared__ __align__(16) __half Bs[32 * BS_ST];

    float acc[4][4][4];
    gemm128_mainloop(g_ctx, Wo, As, Bs, acc);

    const int tid  = threadIdx.x;
    const int warp = tid >> 5;
    const int lane = tid & 31;
    const int gid  = lane >> 2;
    const int t4   = lane & 3;
    const int warp_m = (warp >> 2) * 64;
    const int warp_n = (warp & 3) * 32;
    const int m0 = blockIdx.y * 128;
    const int n0 = blockIdx.x * 128;

#pragma unroll
    for (int mt = 0; mt < 4; mt++) {
        const int mrow = m0 + warp_m + mt * 16 + gid;
#pragma unroll
        for (int nt = 0; nt < 4; nt++) {
            const int n = n0 + warp_n + nt * 8 + t4 * 2;
            const float bx = bo[n], by = bo[n + 1];
            {
                const float* xr = x + (size_t)mrow * HH + n;
                float* yo = g_y + (size_t)mrow * HH + n;
                *(float2*)yo = make_float2(acc[mt][nt][0] + bx + xr[0],
                                           acc[mt][nt][1] + by + xr[1]);
            }
            {
                const float* xr = x + (size_t)(mrow + 8) * HH + n;
                float* yo = g_y + (size_t)(mrow + 8) * HH + n;
                *(float2*)yo = make_float2(acc[mt][nt][2] + bx + xr[0],
                                           acc[mt][nt][3] + by + xr[1]);
            }
        }
    }
}

// ---------------------------------------------------------------------------
// LayerNorm over last dim (1024), one block per row.
// ---------------------------------------------------------------------------
__global__ __launch_bounds__(256) void ln_kernel(
    const float* __restrict__ gamma, const float* __restrict__ beta,
    float* __restrict__ out)
{
    __shared__ float red[256];
    const int row = blockIdx.x;
    const int tid = threadIdx.x;

    const float4* yp = (const float4*)(g_y + (size_t)row * HH);
    float4 v = yp[tid];

    float s = v.x + v.y + v.z + v.w;
    red[tid] = s;
    __syncthreads();
    for (int off = 128; off > 0; off >>= 1) {
        if (tid < off) red[tid] += red[tid + off];
        __syncthreads();
    }
    const float mu = red[0] * (1.0f / HH);
    __syncthreads();

    float dx = v.x - mu, dy = v.y - mu, dz = v.z - mu, dw = v.w - mu;
    red[tid] = dx * dx + dy * dy + dz * dz + dw * dw;
    __syncthreads();
    for (int off = 128; off > 0; off >>= 1) {
        if (tid < off) red[tid] += red[tid + off];
        __syncthreads();
    }
    const float var = red[0] * (1.0f / HH);
    const float inv = rsqrtf(var + 1e-5f);

    const float4 g  = ((const float4*)gamma)[tid];
    const float4 be = ((const float4*)beta)[tid];
    float4 o;
    o.x = dx * inv * g.x + be.x;
    o.y = dy * inv * g.y + be.y;
    o.z = dz * inv * g.z + be.z;
    o.w = dw * inv * g.w + be.w;
    ((float4*)out)[(size_t)row * (HH / 4) + tid] = o;
}

// ---------------------------------------------------------------------------
extern "C" void kernel_launch(void* const* d_in, const int* in_sizes, int n_in,
                              void* d_out, int out_size)
{
    (void)in_sizes; (void)n_in; (void)out_size;
    const float* x  = (const float*)d_in[0];
    const float* Wq = (const float*)d_in[1];
    const float* bq = (const float*)d_in[2];
    const float* Wk = (const float*)d_in[3];
    const float* bk = (const float*)d_in[4];
    const float* Wv = (const float*)d_in[5];
    const float* bv = (const float*)d_in[6];
    const float* Wo = (const float*)d_in[7];
    const float* bo = (const float*)d_in[8];
    const float* ga = (const float*)d_in[9];
    const float* be = (const float*)d_in[10];
    float* out = (float*)d_out;

    dim3 gq(HH / 128, MTOT / 128, 3);
    qkv_gemm_kernel<<<gq, 256>>>(x, Wq, bq, Wk, bk, Wv, bv);

    dim3 gf(SS / 128, BB * NH);
    flash_tc_kernel<<<gf, 256>>>();

    dim3 go(HH / 128, MTOT / 128);
    oproj_gemm_kernel<<<go, 256>>>(x, Wo, bo);

    ln_kernel<<<MTOT, 256>>>(ga, be, out);
}

// round 11
// speedup vs baseline: 6.6160x; 1.2375x over previous
#include <cuda_runtime.h>
#include <cuda_fp16.h>
#include <stdint.h>
#include <math.h>

// Problem constants
static constexpr int BB   = 2;
static constexpr int SS   = 2048;
static constexpr int HH   = 1024;
static constexpr int NH   = 16;
static constexpr int HD   = 64;
static constexpr int MTOT = BB * SS;  // 4096 rows

// Scratch (static device globals)
__device__ __align__(16) __half g_Q[(size_t)BB * NH * SS * HD];  // pre-scaled 0.125
__device__ __align__(16) __half g_K[(size_t)BB * NH * SS * HD];
__device__ __align__(16) __half g_V[(size_t)BB * NH * SS * HD];
__device__ float  g_ctx[(size_t)MTOT * HH];
__device__ float  g_y[(size_t)MTOT * HH];

// ---------------------------------------------------------------------------
// helpers
// ---------------------------------------------------------------------------
__device__ __forceinline__ uint32_t pack2h(float lo, float hi) {
    uint32_t r;
    asm("cvt.rn.f16x2.f32 %0, %1, %2;" : "=r"(r) : "f"(hi), "f"(lo));
    return r;
}
__device__ __forceinline__ void mma16(float c[4], const uint32_t a[4], const uint32_t b[2]) {
    asm volatile(
        "mma.sync.aligned.m16n8k16.row.col.f32.f16.f16.f32 "
        "{%0,%1,%2,%3}, {%4,%5,%6,%7}, {%8,%9}, {%0,%1,%2,%3};"
        : "+f"(c[0]), "+f"(c[1]), "+f"(c[2]), "+f"(c[3])
        : "r"(a[0]), "r"(a[1]), "r"(a[2]), "r"(a[3]), "r"(b[0]), "r"(b[1]));
}
__device__ __forceinline__ void ldsm4(uint32_t r[4], const __half* p) {
    uint32_t a = (uint32_t)__cvta_generic_to_shared(p);
    asm volatile("ldmatrix.sync.aligned.m8n8.x4.shared.b16 {%0,%1,%2,%3}, [%4];"
        : "=r"(r[0]), "=r"(r[1]), "=r"(r[2]), "=r"(r[3]) : "r"(a));
}
__device__ __forceinline__ void ldsm4t(uint32_t r[4], const __half* p) {
    uint32_t a = (uint32_t)__cvta_generic_to_shared(p);
    asm volatile("ldmatrix.sync.aligned.m8n8.x4.trans.shared.b16 {%0,%1,%2,%3}, [%4];"
        : "=r"(r[0]), "=r"(r[1]), "=r"(r[2]), "=r"(r[3]) : "r"(a));
}
__device__ __forceinline__ void cp16(__half* dst, const __half* src) {
    uint32_t d = (uint32_t)__cvta_generic_to_shared(dst);
    asm volatile("cp.async.cg.shared.global [%0], [%1], 16;" :: "r"(d), "l"(src));
}
__device__ __forceinline__ void cp_commit() {
    asm volatile("cp.async.commit_group;");
}
template <int N> __device__ __forceinline__ void cp_wait() {
    asm volatile("cp.async.wait_group %0;" :: "n"(N));
}

// ---------------------------------------------------------------------------
// 128x128x1024 fp16 mma mainloop, double-buffered smem, LDSM frag loads.
// 256 threads, 8 warps (2m x 4n), warp tile 64x32, mma m16n8k16, BK=32.
// As[2][128][40] halfs (m,k);  Bs[2][32][136] halfs (k,n). One sync/ktile.
// ---------------------------------------------------------------------------
static constexpr int AS_ST = 40;
static constexpr int BS_ST = 136;
static constexpr int ABUF  = 128 * AS_ST;   // 5120 halfs
static constexpr int BBUF  = 32 * BS_ST;    // 4352 halfs

__device__ __forceinline__ void gemm128_mainloop(
    const float* __restrict__ A, const float* __restrict__ B,
    __half* As, __half* Bs, float acc[4][4][4])
{
    const int tid  = threadIdx.x;
    const int m0   = blockIdx.y * 128;
    const int n0   = blockIdx.x * 128;
    const int warp = tid >> 5;
    const int lane = tid & 31;
    const int warp_m = (warp >> 2) * 64;
    const int warp_n = (warp & 3) * 32;

    const int arow = tid >> 3, ac4 = tid & 7;
    const int brow = tid >> 5, bc4 = tid & 31;

    // ldmatrix per-lane bases
    const int la = lane & 15, lb = lane >> 4;
    const __half* aF = As + (warp_m + la) * AS_ST + lb * 8;
    const __half* bF = Bs + la * BS_ST + warp_n + lb * 8;

#pragma unroll
    for (int mt = 0; mt < 4; mt++)
#pragma unroll
        for (int nt = 0; nt < 4; nt++)
#pragma unroll
            for (int r = 0; r < 4; r++) acc[mt][nt][r] = 0.0f;

    const float* ag = A + (size_t)(m0 + arow) * HH + ac4 * 4;
    const float* bg = B + (size_t)brow * HH + n0 + bc4 * 4;

    float4 aR[4], bR[4];
#pragma unroll
    for (int r = 0; r < 4; r++) {
        aR[r] = *(const float4*)(ag + (size_t)(32 * r) * HH);
        bR[r] = *(const float4*)(bg + (size_t)(8 * r) * HH);
    }
    // stage tile 0 -> buffer 0
#pragma unroll
    for (int r = 0; r < 4; r++) {
        uint2 av; av.x = pack2h(aR[r].x, aR[r].y); av.y = pack2h(aR[r].z, aR[r].w);
        uint2 bv; bv.x = pack2h(bR[r].x, bR[r].y); bv.y = pack2h(bR[r].z, bR[r].w);
        *(uint2*)&As[(arow + 32 * r) * AS_ST + ac4 * 4] = av;
        *(uint2*)&Bs[(brow + 8 * r) * BS_ST + bc4 * 4]  = bv;
    }
    __syncthreads();

    int cur = 0;
    for (int k0 = 0; k0 < HH; k0 += 32) {
        const bool more = (k0 + 32 < HH);
        if (more) {
            const float* ag2 = ag + (k0 + 32);
            const float* bg2 = bg + (size_t)(k0 + 32) * HH;
#pragma unroll
            for (int r = 0; r < 4; r++) {
                aR[r] = *(const float4*)(ag2 + (size_t)(32 * r) * HH);
                bR[r] = *(const float4*)(bg2 + (size_t)(8 * r) * HH);
            }
        }

        const __half* aFc = aF + cur * ABUF;
        const __half* bFc = bF + cur * BBUF;
#pragma unroll
        for (int ks = 0; ks < 2; ks++) {
            uint32_t Af[4][4];
#pragma unroll
            for (int mt = 0; mt < 4; mt++)
                ldsm4(Af[mt], aFc + mt * 16 * AS_ST + ks * 16);
            uint32_t Bf[4][4];
#pragma unroll
            for (int ntp = 0; ntp < 2; ntp++)
                ldsm4t(Bf[2 * ntp], bFc + ks * 16 * BS_ST + ntp * 16);
            // Bf[2*ntp] = {b0_nt, b1_nt, b0_nt1, b1_nt1} spread over Bf[2ntp..2ntp+1]
#pragma unroll
            for (int mt = 0; mt < 4; mt++) {
                mma16(acc[mt][0], Af[mt], &Bf[0][0]);
                mma16(acc[mt][1], Af[mt], &Bf[0][2]);
                mma16(acc[mt][2], Af[mt], &Bf[2][0]);
                mma16(acc[mt][3], Af[mt], &Bf[2][2]);
            }
        }

        if (more) {
            const int nb = cur ^ 1;
#pragma unroll
            for (int r = 0; r < 4; r++) {
                uint2 av; av.x = pack2h(aR[r].x, aR[r].y); av.y = pack2h(aR[r].z, aR[r].w);
                uint2 bv; bv.x = pack2h(bR[r].x, bR[r].y); bv.y = pack2h(bR[r].z, bR[r].w);
                *(uint2*)&As[nb * ABUF + (arow + 32 * r) * AS_ST + ac4 * 4] = av;
                *(uint2*)&Bs[nb * BBUF + (brow + 8 * r) * BS_ST + bc4 * 4]  = bv;
            }
            __syncthreads();
            cur = nb;
        }
    }
}

// ---------------------------------------------------------------------------
// QKV GEMM: out = x @ W + b (Q scaled by 0.125), fp16 out, head-major scatter.
// ---------------------------------------------------------------------------
__global__ __launch_bounds__(256, 1) void qkv_gemm_kernel(
    const float* __restrict__ x,
    const float* __restrict__ Wq, const float* __restrict__ bq,
    const float* __restrict__ Wk, const float* __restrict__ bk,
    const float* __restrict__ Wv, const float* __restrict__ bv)
{
    const int mat = blockIdx.z;
    const float* W    = (mat == 0) ? Wq : (mat == 1 ? Wk : Wv);
    const float* bias = (mat == 0) ? bq : (mat == 1 ? bk : bv);
    __half* out       = (mat == 0) ? g_Q : (mat == 1 ? g_K : g_V);
    const float osc   = (mat == 0) ? 0.125f : 1.0f;

    __shared__ __align__(16) __half As[2 * ABUF];
    __shared__ __align__(16) __half Bs[2 * BBUF];

    float acc[4][4][4];
    gemm128_mainloop(x, W, As, Bs, acc);

    const int tid  = threadIdx.x;
    const int warp = tid >> 5;
    const int lane = tid & 31;
    const int gid  = lane >> 2;
    const int t4   = lane & 3;
    const int warp_m = (warp >> 2) * 64;
    const int warp_n = (warp & 3) * 32;
    const int m0 = blockIdx.y * 128;
    const int n0 = blockIdx.x * 128;

#pragma unroll
    for (int mt = 0; mt < 4; mt++) {
        const int mrow = m0 + warp_m + mt * 16 + gid;
#pragma unroll
        for (int nt = 0; nt < 4; nt++) {
            const int n = n0 + warp_n + nt * 8 + t4 * 2;
            const int h = n >> 6;
            const int d = n & 63;
            const float bx = bias[n], by = bias[n + 1];
            {
                int b = mrow >> 11, s = mrow & 2047;
                __half* o = out + (((size_t)(b * NH + h) * SS) + s) * HD + d;
                *(uint32_t*)o = pack2h((acc[mt][nt][0] + bx) * osc,
                                       (acc[mt][nt][1] + by) * osc);
            }
            {
                int m2 = mrow + 8;
                int b = m2 >> 11, s = m2 & 2047;
                __half* o = out + (((size_t)(b * NH + h) * SS) + s) * HD + d;
                *(uint32_t*)o = pack2h((acc[mt][nt][2] + bx) * osc,
                                       (acc[mt][nt][3] + by) * osc);
            }
        }
    }
}

// ---------------------------------------------------------------------------
// Flash attention, fp16 m16n8k16, cp.async double-buffered K/V, LDSM frags.
// 256 threads (8 warps) -> 128 q rows; warp w owns rows [w*16, w*16+16).
// smem: 2 buffers x (K 64x72 + V 64x72) = 36.9 KB -> 2 CTAs/SM.
// ---------------------------------------------------------------------------
static constexpr int FK_ST = 72;              // halfs per row
static constexpr int KVBUF = 64 * FK_ST;      // 4608 halfs

__global__ __launch_bounds__(256, 2) void flash_tc_kernel()
{
    __shared__ __align__(16) __half sm[4 * KVBUF];   // 18432 halfs = 36.9 KB

    const int bh  = blockIdx.y;     // b*NH + h
    const int b   = bh >> 4;
    const int h   = bh & 15;
    const int q0  = blockIdx.x * 128;
    const int tid = threadIdx.x;
    const int warp = tid >> 5;
    const int lane = tid & 31;
    const int gid  = lane >> 2;
    const int t4   = lane & 3;
    const int la   = lane & 15;
    const int lb   = lane >> 4;
    const unsigned F = 0xFFFFFFFFu;

    // ---- Stage Q (128 x 64 halfs, pre-scaled) into buffer area, extract frags
    {
        const uint2* Qg = (const uint2*)(g_Q + ((size_t)bh * SS + q0) * HD);
#pragma unroll
        for (int i = 0; i < 8; i++) {
            int idx = tid + i * 256;
            int row = idx >> 4, c4 = idx & 15;
            *(uint2*)&sm[row * FK_ST + c4 * 4] = Qg[idx];
        }
    }
    __syncthreads();

    uint32_t Qa[4][4];
    {
        const __half* qF = sm + (warp * 16 + la) * FK_ST + lb * 8;
#pragma unroll
        for (int ks = 0; ks < 4; ks++)
            ldsm4(Qa[ks], qF + ks * 16);
    }
    __syncthreads();   // Q consumed; buffer 0 free for K/V

    float Oc[8][4];
#pragma unroll
    for (int dt = 0; dt < 8; dt++)
#pragma unroll
        for (int r = 0; r < 4; r++) Oc[dt][r] = 0.0f;
    float m0r = -1e30f, m1r = -1e30f;
    float l0r = 0.0f,   l1r = 0.0f;

    const __half* Kgb = g_K + (size_t)bh * SS * HD;
    const __half* Vgb = g_V + (size_t)bh * SS * HD;

    // per-lane ldmatrix bases for K (non-trans) and V (trans)
    const int krow_l = (lane & 7) + lb * 8;
    const int kcol_l = ((lane >> 3) & 1) * 8;

    auto issue = [&](int kt, int buf) {
        __half* Kd = sm + buf * 2 * KVBUF;
        __half* Vd = Kd + KVBUF;
        const __half* Kg = Kgb + (size_t)kt * 64 * HD;
        const __half* Vg = Vgb + (size_t)kt * 64 * HD;
#pragma unroll
        for (int i = 0; i < 2; i++) {
            int u = tid + i * 256;          // 0..511
            int row = u >> 3, c8 = u & 7;
            cp16(Kd + row * FK_ST + c8 * 8, Kg + row * 64 + c8 * 8);
            cp16(Vd + row * FK_ST + c8 * 8, Vg + row * 64 + c8 * 8);
        }
        cp_commit();
    };

    issue(0, 0);

    for (int kt = 0; kt < SS / 64; kt++) {
        const bool more = (kt + 1 < SS / 64);
        if (more) issue(kt + 1, (kt + 1) & 1);
        if (more) cp_wait<1>(); else cp_wait<0>();
        __syncthreads();

        const __half* Ks = sm + (kt & 1) * 2 * KVBUF;
        const __half* Vs = Ks + KVBUF;

        // ---- S = Q K^T ----
        float S[8][4];
#pragma unroll
        for (int nt = 0; nt < 8; nt++)
            S[nt][0] = S[nt][1] = S[nt][2] = S[nt][3] = 0.0f;
#pragma unroll
        for (int ks = 0; ks < 4; ks++) {
#pragma unroll
            for (int ntp = 0; ntp < 4; ntp++) {
                uint32_t bb[4];
                ldsm4(bb, Ks + (ntp * 16 + krow_l) * FK_ST + ks * 16 + kcol_l);
                mma16(S[2 * ntp],     Qa[ks], bb);
                mma16(S[2 * ntp + 1], Qa[ks], bb + 2);
            }
        }

        // ---- clip + online softmax (rows gid / gid+8) ----
        float tmax0 = -1e30f, tmax1 = -1e30f;
#pragma unroll
        for (int nt = 0; nt < 8; nt++) {
#pragma unroll
            for (int r = 0; r < 4; r++)
                S[nt][r] = fminf(fmaxf(S[nt][r], -10000.0f), 10000.0f);
            tmax0 = fmaxf(tmax0, fmaxf(S[nt][0], S[nt][1]));
            tmax1 = fmaxf(tmax1, fmaxf(S[nt][2], S[nt][3]));
        }
        tmax0 = fmaxf(tmax0, __shfl_xor_sync(F, tmax0, 1));
        tmax0 = fmaxf(tmax0, __shfl_xor_sync(F, tmax0, 2));
        tmax1 = fmaxf(tmax1, __shfl_xor_sync(F, tmax1, 1));
        tmax1 = fmaxf(tmax1, __shfl_xor_sync(F, tmax1, 2));

        float nm0 = fmaxf(m0r, tmax0);
        float nm1 = fmaxf(m1r, tmax1);
        float al0 = __expf(m0r - nm0);
        float al1 = __expf(m1r - nm1);
        m0r = nm0; m1r = nm1;

        float sum0 = 0.0f, sum1 = 0.0f;
#pragma unroll
        for (int nt = 0; nt < 8; nt++) {
            S[nt][0] = __expf(S[nt][0] - nm0);
            S[nt][1] = __expf(S[nt][1] - nm0);
            S[nt][2] = __expf(S[nt][2] - nm1);
            S[nt][3] = __expf(S[nt][3] - nm1);
            sum0 += S[nt][0] + S[nt][1];
            sum1 += S[nt][2] + S[nt][3];
        }
        sum0 += __shfl_xor_sync(F, sum0, 1);
        sum0 += __shfl_xor_sync(F, sum0, 2);
        sum1 += __shfl_xor_sync(F, sum1, 1);
        sum1 += __shfl_xor_sync(F, sum1, 2);
        l0r = l0r * al0 + sum0;
        l1r = l1r * al1 + sum1;

#pragma unroll
        for (int dt = 0; dt < 8; dt++) {
            Oc[dt][0] *= al0; Oc[dt][1] *= al0;
            Oc[dt][2] *= al1; Oc[dt][3] *= al1;
        }

        // ---- ctx += P V : P C-frag -> A-frag directly; V frags via LDSM.trans
#pragma unroll
        for (int ks = 0; ks < 4; ks++) {
            uint32_t Pa[4];
            Pa[0] = pack2h(S[2 * ks][0],     S[2 * ks][1]);
            Pa[1] = pack2h(S[2 * ks][2],     S[2 * ks][3]);
            Pa[2] = pack2h(S[2 * ks + 1][0], S[2 * ks + 1][1]);
            Pa[3] = pack2h(S[2 * ks + 1][2], S[2 * ks + 1][3]);
            const __half* vrow = Vs + (ks * 16 + la) * FK_ST + lb * 8;
#pragma unroll
            for (int dtp = 0; dtp < 4; dtp++) {
                uint32_t bb[4];
                ldsm4t(bb, vrow + dtp * 16);
                mma16(Oc[2 * dtp],     Pa, bb);
                mma16(Oc[2 * dtp + 1], Pa, bb + 2);
            }
        }
        __syncthreads();
    }

    // ---- epilogue ----
    const float inv0 = 1.0f / l0r;
    const float inv1 = 1.0f / l1r;
    const int srow = q0 + warp * 16 + gid;
    float* out0 = g_ctx + ((size_t)(b * SS + srow)) * HH + h * HD;
    float* out1 = out0 + (size_t)8 * HH;
#pragma unroll
    for (int dt = 0; dt < 8; dt++) {
        int c = dt * 8 + t4 * 2;
        *(float2*)(out0 + c) = make_float2(Oc[dt][0] * inv0, Oc[dt][1] * inv0);
        *(float2*)(out1 + c) = make_float2(Oc[dt][2] * inv1, Oc[dt][3] * inv1);
    }
}

// ---------------------------------------------------------------------------
// O projection: y = ctx @ Wo + bo + x
// ---------------------------------------------------------------------------
__global__ __launch_bounds__(256, 1) void oproj_gemm_kernel(
    const float* __restrict__ x,
    const float* __restrict__ Wo, const float* __restrict__ bo)
{
    __shared__ __align__(16) __half As[2 * ABUF];
    __shared__ __align__(16) __half Bs[2 * BBUF];

    float acc[4][4][4];
    gemm128_mainloop(g_ctx, Wo, As, Bs, acc);

    const int tid  = threadIdx.x;
    const int warp = tid >> 5;
    const int lane = tid & 31;
    const int gid  = lane >> 2;
    const int t4   = lane & 3;
    const int warp_m = (warp >> 2) * 64;
    const int warp_n = (warp & 3) * 32;
    const int m0 = blockIdx.y * 128;
    const int n0 = blockIdx.x * 128;

#pragma unroll
    for (int mt = 0; mt < 4; mt++) {
        const int mrow = m0 + warp_m + mt * 16 + gid;
#pragma unroll
        for (int nt = 0; nt < 4; nt++) {
            const int n = n0 + warp_n + nt * 8 + t4 * 2;
            const float bx = bo[n], by = bo[n + 1];
            {
                const float* xr = x + (size_t)mrow * HH + n;
                float* yo = g_y + (size_t)mrow * HH + n;
                *(float2*)yo = make_float2(acc[mt][nt][0] + bx + xr[0],
                                           acc[mt][nt][1] + by + xr[1]);
            }
            {
                const float* xr = x + (size_t)(mrow + 8) * HH + n;
                float* yo = g_y + (size_t)(mrow + 8) * HH + n;
                *(float2*)yo = make_float2(acc[mt][nt][2] + bx + xr[0],
                                           acc[mt][nt][3] + by + xr[1]);
            }
        }
    }
}

// ---------------------------------------------------------------------------
// LayerNorm over last dim (1024): shuffle reduce, one sync.
// ---------------------------------------------------------------------------
__global__ __launch_bounds__(256) void ln_kernel(
    const float* __restrict__ gamma, const float* __restrict__ beta,
    float* __restrict__ out)
{
    __shared__ float red[16];
    const int row = blockIdx.x;
    const int tid = threadIdx.x;
    const int warp = tid >> 5;
    const int lane = tid & 31;
    const unsigned F = 0xFFFFFFFFu;

    const float4* yp = (const float4*)(g_y + (size_t)row * HH);
    float4 v = yp[tid];

    float s  = v.x + v.y + v.z + v.w;
    float sq = v.x * v.x + v.y * v.y + v.z * v.z + v.w * v.w;
#pragma unroll
    for (int off = 16; off > 0; off >>= 1) {
        s  += __shfl_xor_sync(F, s,  off);
        sq += __shfl_xor_sync(F, sq, off);
    }
    if (lane == 0) { red[warp] = s; red[8 + warp] = sq; }
    __syncthreads();

    float ts = 0.0f, tsq = 0.0f;
#pragma unroll
    for (int w = 0; w < 8; w++) { ts += red[w]; tsq += red[8 + w]; }
    const float mu  = ts * (1.0f / HH);
    const float var = tsq * (1.0f / HH) - mu * mu;
    const float inv = rsqrtf(var + 1e-5f);

    const float4 g  = ((const float4*)gamma)[tid];
    const float4 be = ((const float4*)beta)[tid];
    float4 o;
    o.x = (v.x - mu) * inv * g.x + be.x;
    o.y = (v.y - mu) * inv * g.y + be.y;
    o.z = (v.z - mu) * inv * g.z + be.z;
    o.w = (v.w - mu) * inv * g.w + be.w;
    ((float4*)out)[(size_t)row * (HH / 4) + tid] = o;
}

// ---------------------------------------------------------------------------
extern "C" void kernel_launch(void* const* d_in, const int* in_sizes, int n_in,
                              void* d_out, int out_size)
{
    (void)in_sizes; (void)n_in; (void)out_size;
    const float* x  = (const float*)d_in[0];
    const float* Wq = (const float*)d_in[1];
    const float* bq = (const float*)d_in[2];
    const float* Wk = (const float*)d_in[3];
    const float* bk = (const float*)d_in[4];
    const float* Wv = (const float*)d_in[5];
    const float* bv = (const float*)d_in[6];
    const float* Wo = (const float*)d_in[7];
    const float* bo = (const float*)d_in[8];
    const float* ga = (const float*)d_in[9];
    const float* be = (const float*)d_in[10];
    float* out = (float*)d_out;

    dim3 gq(HH / 128, MTOT / 128, 3);
    qkv_gemm_kernel<<<gq, 256>>>(x, Wq, bq, Wk, bk, Wv, bv);

    dim3 gf(SS / 128, BB * NH);
    flash_tc_kernel<<<gf, 256>>>();

    dim3 go(HH / 128, MTOT / 128);
    oproj_gemm_kernel<<<go, 256>>>(x, Wo, bo);

    ln_kernel<<<MTOT, 256>>>(ga, be, out);
}